// round 1
// baseline (speedup 1.0000x reference)
#include <cuda_runtime.h>
#include <cuda_bf16.h>

// Conv4D with rank-1 separable kernel: k4 = K (x) K, K is 3x3.
// out[n,x,y,z,w] = sum_{i,j,p,q} K[i,j]*K[p,q] * in[n,x+i,y+j,z+p,w+q]
// Factored into two 2D passes through shared memory, one CTA per sample n.

#define N_SAMPLES 8192
#define THREADS   256

__global__ __launch_bounds__(THREADS)
void conv4d_sep_kernel(const float* __restrict__ in,
                       const float* __restrict__ kern,
                       float* __restrict__ out) {
    __shared__ float s_in[4096];    // 8x8x8x8 input tile (16 KB)
    __shared__ float s_tmp[2304];   // 8x8x6x6 intermediate (9.2 KB)
    __shared__ float s_k[9];

    const int tid = threadIdx.x;
    const int n   = blockIdx.x;

    if (tid < 9) s_k[tid] = kern[tid];

    // Stage input tile: 4096 floats = 1024 float4, 4 per thread, coalesced.
    const float4* __restrict__ in4 = (const float4*)(in + (size_t)n * 4096);
    float4* s4 = (float4*)s_in;
    #pragma unroll
    for (int i = 0; i < 4; i++) {
        s4[tid + i * THREADS] = in4[tid + i * THREADS];
    }
    __syncthreads();

    const float k00 = s_k[0], k01 = s_k[1], k02 = s_k[2];
    const float k10 = s_k[3], k11 = s_k[4], k12 = s_k[5];
    const float k20 = s_k[6], k21 = s_k[7], k22 = s_k[8];

    // Pass 1: conv over (z,w). tmp[a][b][zc][wc], 2304 items = 9 per thread.
    // in flat: a*512 + b*64 + z*8 + w ; tmp flat: ab*36 + zc*6 + wc
    #pragma unroll
    for (int it = 0; it < 9; it++) {
        const int idx = tid + it * THREADS;
        const int wc  = idx % 6;
        const int zc  = (idx / 6) % 6;
        const int ab  = idx / 36;              // 0..63 combined a,b
        const float* b0 = s_in + ab * 64 + zc * 8 + wc;
        float acc;
        acc  = k00 * b0[0]  + k01 * b0[1]  + k02 * b0[2];
        acc += k10 * b0[8]  + k11 * b0[9]  + k12 * b0[10];
        acc += k20 * b0[16] + k21 * b0[17] + k22 * b0[18];
        s_tmp[idx] = acc;
    }
    __syncthreads();

    // Pass 2: conv over (x,y). out[x][y][z][w], 1296 items.
    // tmp flat: (x+i)*288 + (y+j)*36 + zw ; out flat: x*216 + y*36 + zw
    float* __restrict__ outp = out + (size_t)n * 1296;
    #pragma unroll
    for (int it = 0; it < 6; it++) {
        const int idx = tid + it * THREADS;
        if (idx < 1296) {
            const int zw = idx % 36;
            const int y  = (idx / 36) % 6;
            const int x  = idx / 216;
            const float* b0 = s_tmp + x * 288 + y * 36 + zw;
            float acc;
            acc  = k00 * b0[0]   + k01 * b0[36]  + k02 * b0[72];
            acc += k10 * b0[288] + k11 * b0[324] + k12 * b0[360];
            acc += k20 * b0[576] + k21 * b0[612] + k22 * b0[648];
            outp[idx] = acc;
        }
    }
}

extern "C" void kernel_launch(void* const* d_in, const int* in_sizes, int n_in,
                              void* d_out, int out_size) {
    const float* input  = (const float*)d_in[0];
    const float* kernel = (const float*)d_in[1];
    float* out = (float*)d_out;
    conv4d_sep_kernel<<<N_SAMPLES, THREADS>>>(input, kernel, out);
}

// round 3
// speedup vs baseline: 1.0213x; 1.0213x over previous
#include <cuda_runtime.h>
#include <cuda_bf16.h>

// Conv4D, separable rank-1 kernel k4 = K (x) K with K 3x3.
// Two register-blocked 2D conv passes; only the intermediate touches smem.
// Pass 1: thread owns (sample, a, b) -> loads its 64 contiguous (z,w) floats
//         straight from GMEM (16x float4), produces 36 tmp values in regs.
// Pass 2: thread owns (sample, z, w)-column -> 64 conflict-free scalar LDS,
//         36 outputs in regs, coalesced STG.

#define N_SAMPLES 8192
#define SAMPLES_PER_CTA 4
#define THREADS 256
#define TMP_STRIDE 37          // pad 36 -> 37: conflict-free both access patterns
#define TMP_PER_SAMPLE (64 * TMP_STRIDE)

__global__ __launch_bounds__(THREADS)
void conv4d_sep2_kernel(const float* __restrict__ in,
                        const float* __restrict__ kern,
                        float* __restrict__ out) {
    __shared__ float s_tmp[SAMPLES_PER_CTA * TMP_PER_SAMPLE];  // ~37.9 KB

    const int tid = threadIdx.x;
    const int n0  = blockIdx.x * SAMPLES_PER_CTA;

    float k[9];
    #pragma unroll
    for (int i = 0; i < 9; i++) k[i] = __ldg(kern + i);

    // ---------------- Pass 1: conv over (z,w) ----------------
    {
        const int s  = tid >> 6;    // sample within CTA
        const int ab = tid & 63;    // combined (a,b)
        const float4* __restrict__ src =
            (const float4*)(in + (size_t)(n0 + s) * 4096 + ab * 64);

        float4 r[16];
        #pragma unroll
        for (int i = 0; i < 16; i++) r[i] = __ldg(src + i);

        float acc[36];
        #pragma unroll
        for (int i = 0; i < 36; i++) acc[i] = 0.0f;

        #pragma unroll
        for (int z = 0; z < 8; z++) {
            float row[8];
            row[0] = r[2*z].x;   row[1] = r[2*z].y;
            row[2] = r[2*z].z;   row[3] = r[2*z].w;
            row[4] = r[2*z+1].x; row[5] = r[2*z+1].y;
            row[6] = r[2*z+1].z; row[7] = r[2*z+1].w;
            #pragma unroll
            for (int i = 0; i < 3; i++) {
                const int zc = z - i;
                if (zc >= 0 && zc < 6) {
                    #pragma unroll
                    for (int y = 0; y < 6; y++) {
                        acc[zc*6 + y] += k[i*3+0] * row[y]
                                       + k[i*3+1] * row[y+1]
                                       + k[i*3+2] * row[y+2];
                    }
                }
            }
        }

        float* t = s_tmp + s * TMP_PER_SAMPLE + ab * TMP_STRIDE;
        #pragma unroll
        for (int i = 0; i < 36; i++) t[i] = acc[i];
    }

    __syncthreads();

    // ---------------- Pass 2: conv over (x,y) ----------------
    if (tid < SAMPLES_PER_CTA * 36) {
        const int s  = tid / 36;
        const int zw = tid % 36;
        const float* t = s_tmp + s * TMP_PER_SAMPLE + zw;

        float acc[36];
        #pragma unroll
        for (int i = 0; i < 36; i++) acc[i] = 0.0f;

        #pragma unroll
        for (int a = 0; a < 8; a++) {
            float row[8];
            #pragma unroll
            for (int b = 0; b < 8; b++) row[b] = t[(a*8 + b) * TMP_STRIDE];
            #pragma unroll
            for (int i = 0; i < 3; i++) {
                const int xc = a - i;
                if (xc >= 0 && xc < 6) {
                    #pragma unroll
                    for (int y = 0; y < 6; y++) {
                        acc[xc*6 + y] += k[i*3+0] * row[y]
                                       + k[i*3+1] * row[y+1]
                                       + k[i*3+2] * row[y+2];
                    }
                }
            }
        }

        float* __restrict__ o = out + (size_t)(n0 + s) * 1296 + zw;
        #pragma unroll
        for (int x = 0; x < 6; x++) {
            #pragma unroll
            for (int y = 0; y < 6; y++) {
                o[x*216 + y*36] = acc[x*6 + y];
            }
        }
    }
}

extern "C" void kernel_launch(void* const* d_in, const int* in_sizes, int n_in,
                              void* d_out, int out_size) {
    const float* input  = (const float*)d_in[0];
    const float* kernel = (const float*)d_in[1];
    float* out = (float*)d_out;
    conv4d_sep2_kernel<<<N_SAMPLES / SAMPLES_PER_CTA, THREADS>>>(input, kernel, out);
}

// round 8
// speedup vs baseline: 1.9694x; 1.9284x over previous
#include <cuda_runtime.h>
#include <cuda_bf16.h>
#include <cstdint>

// Conv4D, separable rank-1 kernel k4 = K (x) K, K 3x3.
// Stage input coalesced via cp.async into bank-padded smem; pass1 (z,w conv)
// register-blocked with rolling rows reading conflict-free LDS.128; the
// intermediate reuses the input smem region; pass2 (x,y conv) register-blocked,
// coalesced STG.

#define N_SAMPLES 8192
#define SAMPLES_PER_CTA 2
#define THREADS 128
#define IN_STRIDE 68            // floats per (a,b) column, padded 64->68
#define IN_S (64 * IN_STRIDE)   // 4352 floats per sample
#define TMP_STRIDE 37           // floats per (a,b) row of tmp, padded 36->37
#define TMP_S 2372              // per-sample tmp stride (2368 + 4 for bank shift)

__device__ __forceinline__ uint32_t smem_u32(const void* p) {
    uint32_t a;
    asm("{ .reg .u64 t; cvta.to.shared.u64 t, %1; cvt.u32.u64 %0, t; }"
        : "=r"(a) : "l"(p));
    return a;
}
__device__ __forceinline__ void cp16(uint32_t saddr, const void* g) {
    asm volatile("cp.async.cg.shared.global [%0], [%1], 16;" :: "r"(saddr), "l"(g));
}

__global__ __launch_bounds__(THREADS, 6)
void conv4d_sep3_kernel(const float* __restrict__ in,
                        const float* __restrict__ kern,
                        float* __restrict__ out) {
    __shared__ float s_buf[SAMPLES_PER_CTA * IN_S];   // 34816 B, reused for tmp

    const int tid = threadIdx.x;
    const int n0  = blockIdx.x * SAMPLES_PER_CTA;

    float k[9];
    #pragma unroll
    for (int i = 0; i < 9; i++) k[i] = __ldg(kern + i);

    // ---- Stage: 2048 float4 coalesced, cp.async, zero reg pressure ----
    {
        const float4* __restrict__ gsrc = (const float4*)(in + (size_t)n0 * 4096);
        const uint32_t sbase = smem_u32(s_buf);
        #pragma unroll
        for (int i = 0; i < 16; i++) {
            const int g   = tid + i * THREADS;       // 0..2047
            const int s   = g >> 10;                 // sample
            const int rem = g & 1023;
            const int ab  = rem >> 4;
            const int f   = rem & 15;
            const uint32_t dst = sbase + (uint32_t)(s * IN_S + ab * IN_STRIDE + f * 4) * 4u;
            cp16(dst, gsrc + g);
        }
        asm volatile("cp.async.commit_group;");
        asm volatile("cp.async.wait_group 0;");
    }
    __syncthreads();

    // ---- Pass 1: conv over (z,w), thread owns (s, ab), acc in regs ----
    float acc[36];
    {
        const int s  = tid >> 6;
        const int ab = tid & 63;
        const float* base = s_buf + s * IN_S + ab * IN_STRIDE;

        float r0[8], r1[8], r2[8];
        #pragma unroll
        for (int b = 0; b < 2; b++) {
            float4 v = ((const float4*)(base + 0))[b];
            r0[4*b+0]=v.x; r0[4*b+1]=v.y; r0[4*b+2]=v.z; r0[4*b+3]=v.w;
            float4 u = ((const float4*)(base + 8))[b];
            r1[4*b+0]=u.x; r1[4*b+1]=u.y; r1[4*b+2]=u.z; r1[4*b+3]=u.w;
        }
        #pragma unroll
        for (int zc = 0; zc < 6; zc++) {
            #pragma unroll
            for (int b = 0; b < 2; b++) {
                float4 v = ((const float4*)(base + (zc + 2) * 8))[b];
                r2[4*b+0]=v.x; r2[4*b+1]=v.y; r2[4*b+2]=v.z; r2[4*b+3]=v.w;
            }
            #pragma unroll
            for (int y = 0; y < 6; y++) {
                acc[zc*6+y] = k[0]*r0[y] + k[1]*r0[y+1] + k[2]*r0[y+2]
                            + k[3]*r1[y] + k[4]*r1[y+1] + k[5]*r1[y+2]
                            + k[6]*r2[y] + k[7]*r2[y+1] + k[8]*r2[y+2];
            }
            #pragma unroll
            for (int b = 0; b < 8; b++) { r0[b] = r1[b]; r1[b] = r2[b]; }
        }
    }
    __syncthreads();   // all reads of staged input done

    // ---- Write intermediate into reused smem region (conflict-free) ----
    {
        const int s  = tid >> 6;
        const int ab = tid & 63;
        float* t = s_buf + s * TMP_S + ab * TMP_STRIDE;
        #pragma unroll
        for (int i = 0; i < 36; i++) t[i] = acc[i];
    }
    __syncthreads();

    // ---- Pass 2: conv over (x,y), thread owns (s, zw) ----
    if (tid < SAMPLES_PER_CTA * 36) {
        const int s  = (tid >= 36) ? 1 : 0;
        const int zw = tid - s * 36;
        const float* tb = s_buf + s * TMP_S + zw;
        float* __restrict__ o = out + (size_t)(n0 + s) * 1296 + zw;

        float r0[8], r1[8], r2[8];
        #pragma unroll
        for (int b = 0; b < 8; b++) {
            r0[b] = tb[(0*8 + b) * TMP_STRIDE];
            r1[b] = tb[(1*8 + b) * TMP_STRIDE];
        }
        #pragma unroll
        for (int xc = 0; xc < 6; xc++) {
            #pragma unroll
            for (int b = 0; b < 8; b++) r2[b] = tb[((xc+2)*8 + b) * TMP_STRIDE];
            #pragma unroll
            for (int y = 0; y < 6; y++) {
                float v = k[0]*r0[y] + k[1]*r0[y+1] + k[2]*r0[y+2]
                        + k[3]*r1[y] + k[4]*r1[y+1] + k[5]*r1[y+2]
                        + k[6]*r2[y] + k[7]*r2[y+1] + k[8]*r2[y+2];
                o[xc*216 + y*36] = v;
            }
            #pragma unroll
            for (int b = 0; b < 8; b++) { r0[b] = r1[b]; r1[b] = r2[b]; }
        }
    }
}

extern "C" void kernel_launch(void* const* d_in, const int* in_sizes, int n_in,
                              void* d_out, int out_size) {
    const float* input  = (const float*)d_in[0];
    const float* kernel = (const float*)d_in[1];
    float* out = (float*)d_out;
    conv4d_sep3_kernel<<<N_SAMPLES / SAMPLES_PER_CTA, THREADS>>>(input, kernel, out);
}